// round 12
// baseline (speedup 1.0000x reference)
#include <cuda_runtime.h>

#define BN 64
#define TN 512
#define LN 48
#define CL 32            // chunk length (steps)
#define NC 16            // chunks per batch = TN/CL
#define START_I 46
#define PAD_I 45
#define END_I 47

__device__ float g_dir[BN][NC][LN];   // chunk-from-ones output directions
__device__ unsigned g_flag[BN][NC];   // zero-init; consumer resets after read
__device__ float g_S[BN][NC];         // per-chunk log-magnitudes (true directions)
__device__ float g_tailEND[BN];       // log(d_END/sum) of last chunk
__device__ float g_tg[BN];
__device__ float g_val[BN];
__device__ unsigned g_bd[BN];         // per-batch arrival counters (self-reset)
__device__ unsigned g_done;           // global arrival counter (self-reset)

#define FMA_F32X2(d, a, b, c) \
    asm("fma.rn.f32x2 %0, %1, %2, %3;" : "=l"(d) : "l"(a), "l"(b), "l"(c))
#define ADD_F32X2_(d, a, b) \
    asm("add.rn.f32x2 %0, %1, %2;" : "=l"(d) : "l"(a), "l"(b))
#define PACK_F32X2_(d, lo, hi) \
    asm("mov.b64 %0, {%1, %2};" : "=l"(d) : "f"(lo), "f"(hi))
#define UNPACK_F32X2_(lo, hi, s) \
    asm("mov.b64 {%0, %1}, %2;" : "=f"(lo), "=f"(hi) : "l"(s))

// Validated single-warp CL-step scan (round 10); __syncwarp only, no bar.sync.
// Lane t < 24 owns columns (2t, 2t+1); u in scaled linear domain.
__device__ __forceinline__ void chunk_scan_fw(
    const float* __restrict__ scp, const int* __restrict__ mp,
    const unsigned long long* Ea, const unsigned long long* Eb,
    float& u0, float& u1, bool act, int lane,
    float sh_w[2][LN], int sh_k[2], int* K_out)
{
    int K = 0, kcur = 0;
    if (lane == 0) { sh_k[0] = 0; sh_k[1] = 0; }

    float es0[4], es1[4];
    int mb[4];
#pragma unroll
    for (int q = 0; q < 4; q++) {
        const float2 sv = *(const float2*)(scp + q * LN);
        es0[q] = __expf(sv.x);
        es1[q] = __expf(sv.y);
        mb[q] = mp[q];
    }

    float w0 = u0 * es0[0], w1 = u1 * es1[0];
    __syncwarp();

    for (int t0 = 0; t0 < CL; t0 += 4) {
#pragma unroll
        for (int k = 0; k < 4; k++) {
            const int t = t0 + k;
            const int p = t & 1;
            const int msk = mb[k];

            if (act) {
                unsigned long long wp;
                PACK_F32X2_(wp, w0, w1);
                *(unsigned long long*)&sh_w[p][2 * lane] = wp;  // STS.64
            }
            __syncwarp();

            const int knext = sh_k[p ^ 1];
            const float scn = __int_as_float((127 - knext) << 23);
            K += kcur;
            const float sc_cur = __int_as_float((127 - kcur) << 23);

            // dual column dot: 12 LDS.128 (broadcast) + 48 FFMA2
            const ulonglong2* w2 = (const ulonglong2*)sh_w[p];
            unsigned long long a0 = 0ull, a1 = 0ull, a2 = 0ull, a3 = 0ull;
            unsigned long long b0 = 0ull, b1 = 0ull, b2 = 0ull, b3 = 0ull;
#pragma unroll
            for (int q = 0; q < LN / 4; q++) {
                const ulonglong2 wq = w2[q];
                if ((q & 1) == 0) {
                    FMA_F32X2(a0, wq.x, Ea[2 * q],     a0);
                    FMA_F32X2(a1, wq.y, Ea[2 * q + 1], a1);
                    FMA_F32X2(b0, wq.x, Eb[2 * q],     b0);
                    FMA_F32X2(b1, wq.y, Eb[2 * q + 1], b1);
                } else {
                    FMA_F32X2(a2, wq.x, Ea[2 * q],     a2);
                    FMA_F32X2(a3, wq.y, Ea[2 * q + 1], a3);
                    FMA_F32X2(b2, wq.x, Eb[2 * q],     b2);
                    FMA_F32X2(b3, wq.y, Eb[2 * q + 1], b3);
                }
            }
            unsigned long long sA, sB, x, y;
            ADD_F32X2_(x, a0, a1);
            ADD_F32X2_(y, a2, a3);
            ADD_F32X2_(sA, x, y);
            ADD_F32X2_(x, b0, b1);
            ADD_F32X2_(y, b2, b3);
            ADD_F32X2_(sB, x, y);
            float lo, hi;
            UNPACK_F32X2_(lo, hi, sA);
            const float acc0 = lo + hi;
            UNPACK_F32X2_(lo, hi, sB);
            const float acc1 = lo + hi;

            u0 = msk ? acc0 : u0 * sc_cur;
            u1 = msk ? acc1 : u1 * sc_cur;

            if (lane == 0) sh_k[p] = (__float_as_int(u0) >> 23) - 127;  // column 0

            w0 = u0 * es0[(k + 1) & 3] * scn;
            w1 = u1 * es1[(k + 1) & 3] * scn;
            kcur = knext;

            if (t0 + 4 < CL) {
                const float2 sv = *(const float2*)(scp + (t0 + 4 + k) * LN);
                es0[k] = __expf(sv.x);
                es1[k] = __expf(sv.y);
                mb[k] = mp[t0 + 4 + k];
            }
        }
    }
    *K_out = K;
}

__device__ __forceinline__ float sumvec(const float sh[LN])
{
    float sum = 0.f;
    const float4* v4 = (const float4*)sh;
#pragma unroll
    for (int q = 0; q < LN / 4; q++) {
        const float4 v = v4[q];
        sum += (v.x + v.y) + (v.z + v.w);
    }
    return sum;
}

__device__ __forceinline__ float warp_sum(float v)
{
    v += __shfl_xor_sync(0xffffffffu, v, 16);
    v += __shfl_xor_sync(0xffffffffu, v, 8);
    v += __shfl_xor_sync(0xffffffffu, v, 4);
    v += __shfl_xor_sync(0xffffffffu, v, 2);
    v += __shfl_xor_sync(0xffffffffu, v, 1);
    return v;
}

// grid = BN*NC = 1024 single-warp CTAs; <= 12 CTA/SM occupancy => entire grid is
// wave-1 resident, so cross-CTA spin-waits always resolve (every producer runs).
//   c = 0      : ONE scan from ones (ones IS the true init); publish dir[0]; S_0.
//   c = 1..14  : scan1 from ones -> publish dir[c]; spin dir[c-1]; scan2 (L1-hot) -> S_c.
//   c = 15     : tg gold energy during the wait; spin dir[14]; scan2 -> S_15 + tail.
__global__ __launch_bounds__(32) void crf_fused_kernel(
    const float* __restrict__ scores,
    const void* __restrict__ gold_raw,
    const int* __restrict__ mask,
    const float* __restrict__ trans,
    float* __restrict__ out)
{
    const int bid = blockIdx.x;
    const int b = bid >> 4;
    const int c = bid & (NC - 1);
    const int lane = threadIdx.x;
    const bool act = (lane < LN / 2);
    const int j0 = act ? 2 * lane : 0;
    const int j1 = act ? 2 * lane + 1 : 0;

    __shared__ float sh_w[2][LN];
    __shared__ int sh_k[2];

    // E columns for this lane's pair, packed over i-pairs; exp(-10000) == 0
    unsigned long long Ea[LN / 2], Eb[LN / 2];
#pragma unroll
    for (int q = 0; q < LN / 2; q++) {
        float lo = __expf(trans[(2 * q) * LN + j0]);
        float hi = __expf(trans[(2 * q + 1) * LN + j0]);
        PACK_F32X2_(Ea[q], lo, hi);
        lo = __expf(trans[(2 * q) * LN + j1]);
        hi = __expf(trans[(2 * q + 1) * LN + j1]);
        PACK_F32X2_(Eb[q], lo, hi);
    }

    const float* scp = scores + ((size_t)b * TN + c * CL) * LN + j0;
    const int*   mp  = mask + (size_t)b * TN + c * CL;

    float S;

    if (c < NC - 1) {
        // ---- scan1: from ones; publish direction ----
        float u0 = 1.0f, u1 = 1.0f;
        int K;
        chunk_scan_fw(scp, mp, Ea, Eb, u0, u1, act, lane, sh_w, sh_k, &K);

        if (act) {
            unsigned long long up;
            PACK_F32X2_(up, u0, u1);
            *(unsigned long long*)&sh_w[0][2 * lane] = up;
        }
        __syncwarp();
        const float sum = sumvec(sh_w[0]);
        if (act) {
            float2* dp = (float2*)&g_dir[b][c][2 * lane];
            *dp = make_float2(u0 / sum, u1 / sum);
        }
        __threadfence();
        __syncwarp();
        if (lane == 0) g_flag[b][c] = 1u;

        S = (float)K * 0.6931471805599453f + logf(sum);   // final S_0 for c==0
    } else {
        // ---- c == 15: tg gold-path energy (overlaps the dir[14] wait) ----
        // gold declared int64; JAX (x64 off) materializes int32 — detect via ballot:
        // true int64 => every odd 32-bit word is 0 (labels < 48).
        const int* g32 = (const int*)gold_raw;
        const int ok = (g32[2 * lane + 1] == 0) && (g32[2 * (lane + 32) + 1] == 0);
        const int is64 = (__ballot_sync(0xffffffffu, ok) == 0xffffffffu);

        float sum = 0.f;
#pragma unroll
        for (int t = lane; t < TN; t += 32) {
            const long long li = (long long)b * TN + t;
            const int g = is64 ? g32[2 * li] : g32[li];   // little-endian low word
            const float v = scores[li * LN] + trans[g];   // crf[t+1,b,0,g]
            if (mask[li]) sum += v;
        }
        if (lane == 0) sum += trans[START_I];             // t=0 term: trans[0][START]

        sum = warp_sum(sum);
        if (lane == 0) g_tg[b] = sum;
        __threadfence();
        S = 0.f;
    }

    if (c > 0) {
        // ---- spin for predecessor's direction (producer is wave-1 resident) ----
        if (lane == 0) {
            volatile unsigned* f = &g_flag[b][c - 1];
            while (*f == 0u) __nanosleep(64);
            *f = 0u;                // single consumer; reset for next graph replay
            __threadfence();
        }
        __syncwarp();

        float u0, u1;
        {
            const float2 dv = *(const float2*)&g_dir[b][c - 1][j0];
            u0 = act ? dv.x : 1.0f;
            u1 = act ? dv.y : 1.0f;
        }

        // ---- scan2: from true direction (scores are L1-hot for c<15) ----
        int K;
        chunk_scan_fw(scp, mp, Ea, Eb, u0, u1, act, lane, sh_w, sh_k, &K);

        if (act) {
            unsigned long long up;
            PACK_F32X2_(up, u0, u1);
            *(unsigned long long*)&sh_w[0][2 * lane] = up;
        }
        __syncwarp();
        const float sum = sumvec(sh_w[0]);
        S = (float)K * 0.6931471805599453f + logf(sum);

        if (c == NC - 1 && lane == (END_I >> 1))    // lane 23 owns column 47 = END
            g_tailEND[b] = logf(u1) - logf(sum);
    }

    if (lane == 0) g_S[b][c] = S;
    __threadfence();

    // ---- per-batch arrival; last of NC CTAs stitches ----
    unsigned r = 0;
    if (lane == 0) r = atomicAdd(&g_bd[b], 1u);
    r = __shfl_sync(0xffffffffu, r, 0);
    if (r == NC - 1) {
        __threadfence();
        float s = (lane < NC) ? g_S[b][lane] : 0.f;     // normalization logs telescope;
        s = warp_sum(s);                                 // log48 cancels (validated r9)
        const float val = s + g_tailEND[b] - g_tg[b];
        if (lane == 0) {
            g_val[b] = val;
            g_bd[b] = 0u;                 // reset for next graph replay
        }
        __threadfence();
        unsigned r2 = 0;
        if (lane == 0) r2 = atomicAdd(&g_done, 1u);
        r2 = __shfl_sync(0xffffffffu, r2, 0);
        if (r2 == BN - 1) {               // last batch: deterministic final combine
            __threadfence();
            float v = g_val[lane] + g_val[lane + 32];
            v = warp_sum(v);
            if (lane == 0) {
                out[0] = v / (float)BN;
                g_done = 0u;              // reset for next graph replay
            }
        }
    }
}

extern "C" void kernel_launch(void* const* d_in, const int* in_sizes, int n_in,
                              void* d_out, int out_size)
{
    const float* scores = (const float*)d_in[0];
    const void*  gold   = (const void*)d_in[1];
    const int*   mask   = (const int*)d_in[2];
    const float* trans  = (const float*)d_in[3];
    float*       out    = (float*)d_out;

    crf_fused_kernel<<<BN * NC, 32>>>(scores, gold, mask, trans, out);
}

// round 13
// speedup vs baseline: 2.1431x; 2.1431x over previous
#include <cuda_runtime.h>

#define BN 64
#define TN 512
#define LN 48
#define CL 32            // chunk length (true steps)
#define WU 16            // warmup steps (direction recovery)
#define NC 16            // chunks per batch = TN/CL
#define START_I 46
#define PAD_I 45
#define END_I 47

__device__ float g_S[BN][NC];         // per-chunk log-magnitude gains
__device__ float g_tailEND[BN];       // log(u_END/sum) of last chunk
__device__ float g_tg[BN];
__device__ float g_val[BN];
__device__ unsigned g_bd[BN];         // per-batch arrival counters (self-reset)
__device__ unsigned g_done;           // global arrival counter (self-reset)

#define FMA_F32X2(d, a, b, c) \
    asm("fma.rn.f32x2 %0, %1, %2, %3;" : "=l"(d) : "l"(a), "l"(b), "l"(c))
#define ADD_F32X2_(d, a, b) \
    asm("add.rn.f32x2 %0, %1, %2;" : "=l"(d) : "l"(a), "l"(b))
#define PACK_F32X2_(d, lo, hi) \
    asm("mov.b64 %0, {%1, %2};" : "=l"(d) : "f"(lo), "f"(hi))
#define UNPACK_F32X2_(lo, hi, s) \
    asm("mov.b64 {%0, %1}, %2;" : "=f"(lo), "=f"(hi) : "l"(s))

// Validated single-warp scan (round 10); __syncwarp only, STEPS templated.
// Lane t < 24 owns columns (2t, 2t+1); u in scaled linear domain:
// on return, actual vector = u_returned * 2^{K}, K accumulated THIS call only.
template <int STEPS>
__device__ __forceinline__ void chunk_scan(
    const float* __restrict__ scp, const int* __restrict__ mp,
    const unsigned long long* Ea, const unsigned long long* Eb,
    float& u0, float& u1, bool act, int lane,
    float sh_w[2][LN], int sh_k[2], int* K_out)
{
    int K = 0, kcur = 0;
    if (lane == 0) { sh_k[0] = 0; sh_k[1] = 0; }

    float es0[4], es1[4];
    int mb[4];
#pragma unroll
    for (int q = 0; q < 4; q++) {
        const float2 sv = *(const float2*)(scp + q * LN);
        es0[q] = __expf(sv.x);
        es1[q] = __expf(sv.y);
        mb[q] = mp[q];
    }

    float w0 = u0 * es0[0], w1 = u1 * es1[0];
    __syncwarp();

    for (int t0 = 0; t0 < STEPS; t0 += 4) {
#pragma unroll
        for (int k = 0; k < 4; k++) {
            const int t = t0 + k;
            const int p = t & 1;
            const int msk = mb[k];

            if (act) {
                unsigned long long wp;
                PACK_F32X2_(wp, w0, w1);
                *(unsigned long long*)&sh_w[p][2 * lane] = wp;  // STS.64
            }
            __syncwarp();

            const int knext = sh_k[p ^ 1];
            const float scn = __int_as_float((127 - knext) << 23);
            K += kcur;
            const float sc_cur = __int_as_float((127 - kcur) << 23);

            // dual column dot: 12 LDS.128 (broadcast) + 48 FFMA2
            const ulonglong2* w2 = (const ulonglong2*)sh_w[p];
            unsigned long long a0 = 0ull, a1 = 0ull, a2 = 0ull, a3 = 0ull;
            unsigned long long b0 = 0ull, b1 = 0ull, b2 = 0ull, b3 = 0ull;
#pragma unroll
            for (int q = 0; q < LN / 4; q++) {
                const ulonglong2 wq = w2[q];
                if ((q & 1) == 0) {
                    FMA_F32X2(a0, wq.x, Ea[2 * q],     a0);
                    FMA_F32X2(a1, wq.y, Ea[2 * q + 1], a1);
                    FMA_F32X2(b0, wq.x, Eb[2 * q],     b0);
                    FMA_F32X2(b1, wq.y, Eb[2 * q + 1], b1);
                } else {
                    FMA_F32X2(a2, wq.x, Ea[2 * q],     a2);
                    FMA_F32X2(a3, wq.y, Ea[2 * q + 1], a3);
                    FMA_F32X2(b2, wq.x, Eb[2 * q],     b2);
                    FMA_F32X2(b3, wq.y, Eb[2 * q + 1], b3);
                }
            }
            unsigned long long sA, sB, x, y;
            ADD_F32X2_(x, a0, a1);
            ADD_F32X2_(y, a2, a3);
            ADD_F32X2_(sA, x, y);
            ADD_F32X2_(x, b0, b1);
            ADD_F32X2_(y, b2, b3);
            ADD_F32X2_(sB, x, y);
            float lo, hi;
            UNPACK_F32X2_(lo, hi, sA);
            const float acc0 = lo + hi;
            UNPACK_F32X2_(lo, hi, sB);
            const float acc1 = lo + hi;

            u0 = msk ? acc0 : u0 * sc_cur;
            u1 = msk ? acc1 : u1 * sc_cur;

            if (lane == 0) sh_k[p] = (__float_as_int(u0) >> 23) - 127;  // column 0

            w0 = u0 * es0[(k + 1) & 3] * scn;
            w1 = u1 * es1[(k + 1) & 3] * scn;
            kcur = knext;

            if (t0 + 4 < STEPS) {
                const float2 sv = *(const float2*)(scp + (t0 + 4 + k) * LN);
                es0[k] = __expf(sv.x);
                es1[k] = __expf(sv.y);
                mb[k] = mp[t0 + 4 + k];
            }
        }
    }
    *K_out = K;
}

__device__ __forceinline__ float sumvec(const float sh[LN])
{
    float sum = 0.f;
    const float4* v4 = (const float4*)sh;
#pragma unroll
    for (int q = 0; q < LN / 4; q++) {
        const float4 v = v4[q];
        sum += (v.x + v.y) + (v.z + v.w);
    }
    return sum;
}

__device__ __forceinline__ float warp_sum(float v)
{
    v += __shfl_xor_sync(0xffffffffu, v, 16);
    v += __shfl_xor_sync(0xffffffffu, v, 8);
    v += __shfl_xor_sync(0xffffffffu, v, 4);
    v += __shfl_xor_sync(0xffffffffu, v, 2);
    v += __shfl_xor_sync(0xffffffffu, v, 1);
    return v;
}

// grid = BN*NC scan CTAs + BN tg CTAs; ALL independent (no cross-CTA dataflow).
//   c = 0      : 32 exact steps from ones (ones IS the true init). S_0 = K ln2 + log(sum).
//   c = 1..15  : 16 warmup steps from ones starting at t=c*32-16 (recovers incoming
//                direction locally; warmup scale cancels in the ratio), then the 32
//                true steps. S_c = K2 ln2 + log(sum_end) - log(sum_16).
//   fs_END = sum_c S_c + log(u_END/sum_end)|_{c=15}   (normalizations telescope)
__global__ __launch_bounds__(32) void crf_main_kernel(
    const float* __restrict__ scores,
    const void* __restrict__ gold_raw,
    const int* __restrict__ mask,
    const float* __restrict__ trans,
    float* __restrict__ out)
{
    const int bid = blockIdx.x;
    const int lane = threadIdx.x;
    const bool act = (lane < LN / 2);

    __shared__ float sh_w[2][LN];
    __shared__ int sh_k[2];

    int b;
    if (bid < BN * NC) {
        b = bid >> 4;
        const int c = bid & (NC - 1);
        const int j0 = act ? 2 * lane : 0;
        const int j1 = act ? 2 * lane + 1 : 0;

        // E columns for this lane's pair, packed over i-pairs; exp(-10000) == 0
        unsigned long long Ea[LN / 2], Eb[LN / 2];
#pragma unroll
        for (int q = 0; q < LN / 2; q++) {
            float lo = __expf(trans[(2 * q) * LN + j0]);
            float hi = __expf(trans[(2 * q + 1) * LN + j0]);
            PACK_F32X2_(Ea[q], lo, hi);
            lo = __expf(trans[(2 * q) * LN + j1]);
            hi = __expf(trans[(2 * q + 1) * LN + j1]);
            PACK_F32X2_(Eb[q], lo, hi);
        }

        float u0 = 1.0f, u1 = 1.0f;
        float log_in = 0.f;          // log(sum at start of the true chunk)

        if (c > 0) {
            // ---- warmup: WU steps ending at t = c*CL, from ones ----
            const float* scw = scores + ((size_t)b * TN + c * CL - WU) * LN + j0;
            const int*   mpw = mask + (size_t)b * TN + c * CL - WU;
            int Kw;
            chunk_scan<WU>(scw, mpw, Ea, Eb, u0, u1, act, lane, sh_w, sh_k, &Kw);

            if (act) {
                unsigned long long up;
                PACK_F32X2_(up, u0, u1);
                *(unsigned long long*)&sh_w[0][2 * lane] = up;
            }
            __syncwarp();
            log_in = logf(sumvec(sh_w[0]));   // warmup K cancels in the ratio
        }

        // ---- true chunk: CL steps ----
        const float* scp = scores + ((size_t)b * TN + c * CL) * LN + j0;
        const int*   mp  = mask + (size_t)b * TN + c * CL;
        int K;
        chunk_scan<CL>(scp, mp, Ea, Eb, u0, u1, act, lane, sh_w, sh_k, &K);

        if (act) {
            unsigned long long up;
            PACK_F32X2_(up, u0, u1);
            *(unsigned long long*)&sh_w[0][2 * lane] = up;
        }
        __syncwarp();
        const float sum = sumvec(sh_w[0]);

        if (lane == 0)
            g_S[b][c] = (float)K * 0.6931471805599453f + logf(sum) - log_in;

        if (c == NC - 1 && lane == (END_I >> 1))   // lane 23 owns column 47 = END
            g_tailEND[b] = logf(u1) - logf(sum);
    } else {
        // ---- tg gold-path energy (one warp per batch) ----
        b = bid - BN * NC;

        // gold declared int64; JAX (x64 off) materializes int32 — detect via ballot:
        // true int64 => every odd 32-bit word is 0 (labels < 48).
        const int* g32 = (const int*)gold_raw;
        const int ok = (g32[2 * lane + 1] == 0) && (g32[2 * (lane + 32) + 1] == 0);
        const int is64 = (__ballot_sync(0xffffffffu, ok) == 0xffffffffu);

        float sum = 0.f;
#pragma unroll
        for (int t = lane; t < TN; t += 32) {
            const long long li = (long long)b * TN + t;
            const int g = is64 ? g32[2 * li] : g32[li];   // little-endian low word
            const float v = scores[li * LN] + trans[g];   // crf[t+1,b,0,g]
            if (mask[li]) sum += v;
        }
        if (lane == 0) sum += trans[START_I];             // t=0 term: trans[0][START]

        sum = warp_sum(sum);
        if (lane == 0) g_tg[b] = sum;
    }

    // ---- per-batch arrival; last of NC+1 CTAs stitches ----
    __threadfence();
    unsigned r = 0;
    if (lane == 0) r = atomicAdd(&g_bd[b], 1u);
    r = __shfl_sync(0xffffffffu, r, 0);
    if (r == NC) {                        // 17th arrival
        __threadfence();
        float s = (lane < NC) ? g_S[b][lane] : 0.f;
        s = warp_sum(s);
        const float val = s + g_tailEND[b] - g_tg[b];
        if (lane == 0) {
            g_val[b] = val;
            g_bd[b] = 0u;                 // reset for next graph replay
        }
        __threadfence();
        unsigned r2 = 0;
        if (lane == 0) r2 = atomicAdd(&g_done, 1u);
        r2 = __shfl_sync(0xffffffffu, r2, 0);
        if (r2 == BN - 1) {               // last batch: deterministic final combine
            __threadfence();
            float v = g_val[lane] + g_val[lane + 32];
            v = warp_sum(v);
            if (lane == 0) {
                out[0] = v / (float)BN;
                g_done = 0u;              // reset for next graph replay
            }
        }
    }
}

extern "C" void kernel_launch(void* const* d_in, const int* in_sizes, int n_in,
                              void* d_out, int out_size)
{
    const float* scores = (const float*)d_in[0];
    const void*  gold   = (const void*)d_in[1];
    const int*   mask   = (const int*)d_in[2];
    const float* trans  = (const float*)d_in[3];
    float*       out    = (float*)d_out;

    crf_main_kernel<<<BN * NC + BN, 32>>>(scores, gold, mask, trans, out);
}

// round 14
// speedup vs baseline: 2.3756x; 1.1085x over previous
#include <cuda_runtime.h>

#define BN 64
#define TN 512
#define LN 48
#define CL 32            // chunk length (true steps)
#define WU 8             // warmup steps (direction recovery; contraction ~0.37/step)
#define NC 16            // chunks per batch = TN/CL
#define START_I 46
#define PAD_I 45
#define END_I 47

__device__ float g_S[BN][NC];         // per-chunk log-magnitude gains
__device__ float g_tailEND[BN];       // log(u_END/sum) of last chunk
__device__ float g_tg[BN];
__device__ float g_val[BN];
__device__ unsigned g_bd[BN];         // per-batch arrival counters (self-reset)
__device__ unsigned g_done;           // global arrival counter (self-reset)

#define FMA_F32X2(d, a, b, c) \
    asm("fma.rn.f32x2 %0, %1, %2, %3;" : "=l"(d) : "l"(a), "l"(b), "l"(c))
#define ADD_F32X2_(d, a, b) \
    asm("add.rn.f32x2 %0, %1, %2;" : "=l"(d) : "l"(a), "l"(b))
#define PACK_F32X2_(d, lo, hi) \
    asm("mov.b64 %0, {%1, %2};" : "=l"(d) : "f"(lo), "f"(hi))
#define UNPACK_F32X2_(lo, hi, s) \
    asm("mov.b64 {%0, %1}, %2;" : "=f"(lo), "=f"(hi) : "l"(s))

// Validated single-warp scan (round 10/13); __syncwarp only, STEPS templated.
// Lane t < 24 owns columns (2t, 2t+1); u in scaled linear domain:
// on return, actual vector = u_returned * 2^{K}, K accumulated THIS call only.
template <int STEPS>
__device__ __forceinline__ void chunk_scan(
    const float* __restrict__ scp, const int* __restrict__ mp,
    const unsigned long long* Ea, const unsigned long long* Eb,
    float& u0, float& u1, bool act, int lane,
    float sh_w[2][LN], int sh_k[2], int* K_out)
{
    int K = 0, kcur = 0;
    if (lane == 0) { sh_k[0] = 0; sh_k[1] = 0; }

    float es0[4], es1[4];
    int mb[4];
#pragma unroll
    for (int q = 0; q < 4; q++) {
        const float2 sv = *(const float2*)(scp + q * LN);
        es0[q] = __expf(sv.x);
        es1[q] = __expf(sv.y);
        mb[q] = mp[q];
    }

    float w0 = u0 * es0[0], w1 = u1 * es1[0];
    __syncwarp();

    for (int t0 = 0; t0 < STEPS; t0 += 4) {
#pragma unroll
        for (int k = 0; k < 4; k++) {
            const int t = t0 + k;
            const int p = t & 1;
            const int msk = mb[k];

            if (act) {
                unsigned long long wp;
                PACK_F32X2_(wp, w0, w1);
                *(unsigned long long*)&sh_w[p][2 * lane] = wp;  // STS.64
            }
            __syncwarp();

            const int knext = sh_k[p ^ 1];
            const float scn = __int_as_float((127 - knext) << 23);
            K += kcur;
            const float sc_cur = __int_as_float((127 - kcur) << 23);

            // dual column dot: 12 LDS.128 (broadcast) + 48 FFMA2
            const ulonglong2* w2 = (const ulonglong2*)sh_w[p];
            unsigned long long a0 = 0ull, a1 = 0ull, a2 = 0ull, a3 = 0ull;
            unsigned long long b0 = 0ull, b1 = 0ull, b2 = 0ull, b3 = 0ull;
#pragma unroll
            for (int q = 0; q < LN / 4; q++) {
                const ulonglong2 wq = w2[q];
                if ((q & 1) == 0) {
                    FMA_F32X2(a0, wq.x, Ea[2 * q],     a0);
                    FMA_F32X2(a1, wq.y, Ea[2 * q + 1], a1);
                    FMA_F32X2(b0, wq.x, Eb[2 * q],     b0);
                    FMA_F32X2(b1, wq.y, Eb[2 * q + 1], b1);
                } else {
                    FMA_F32X2(a2, wq.x, Ea[2 * q],     a2);
                    FMA_F32X2(a3, wq.y, Ea[2 * q + 1], a3);
                    FMA_F32X2(b2, wq.x, Eb[2 * q],     b2);
                    FMA_F32X2(b3, wq.y, Eb[2 * q + 1], b3);
                }
            }
            unsigned long long sA, sB, x, y;
            ADD_F32X2_(x, a0, a1);
            ADD_F32X2_(y, a2, a3);
            ADD_F32X2_(sA, x, y);
            ADD_F32X2_(x, b0, b1);
            ADD_F32X2_(y, b2, b3);
            ADD_F32X2_(sB, x, y);
            float lo, hi;
            UNPACK_F32X2_(lo, hi, sA);
            const float acc0 = lo + hi;
            UNPACK_F32X2_(lo, hi, sB);
            const float acc1 = lo + hi;

            u0 = msk ? acc0 : u0 * sc_cur;
            u1 = msk ? acc1 : u1 * sc_cur;

            if (lane == 0) sh_k[p] = (__float_as_int(u0) >> 23) - 127;  // column 0

            w0 = u0 * es0[(k + 1) & 3] * scn;
            w1 = u1 * es1[(k + 1) & 3] * scn;
            kcur = knext;

            if (t0 + 4 < STEPS) {
                const float2 sv = *(const float2*)(scp + (t0 + 4 + k) * LN);
                es0[k] = __expf(sv.x);
                es1[k] = __expf(sv.y);
                mb[k] = mp[t0 + 4 + k];
            }
        }
    }
    *K_out = K;
}

__device__ __forceinline__ float sumvec(const float sh[LN])
{
    float sum = 0.f;
    const float4* v4 = (const float4*)sh;
#pragma unroll
    for (int q = 0; q < LN / 4; q++) {
        const float4 v = v4[q];
        sum += (v.x + v.y) + (v.z + v.w);
    }
    return sum;
}

__device__ __forceinline__ float warp_sum(float v)
{
    v += __shfl_xor_sync(0xffffffffu, v, 16);
    v += __shfl_xor_sync(0xffffffffu, v, 8);
    v += __shfl_xor_sync(0xffffffffu, v, 4);
    v += __shfl_xor_sync(0xffffffffu, v, 2);
    v += __shfl_xor_sync(0xffffffffu, v, 1);
    return v;
}

// grid = BN*NC scan CTAs + BN tg CTAs; ALL independent (no cross-CTA dataflow).
//   c = 0      : 32 exact steps from ones (ones IS the true init). S_0 = K ln2 + log(sum).
//   c = 1..15  : WU warmup steps from ones starting at t=c*32-WU (recovers incoming
//                direction locally; warmup scale cancels in the ratio), then the 32
//                true steps. S_c = K2 ln2 + log(sum_end) - log(sum_warm).
//   fs_END = sum_c S_c + log(u_END/sum_end)|_{c=15}   (normalizations telescope)
__global__ __launch_bounds__(32) void crf_main_kernel(
    const float* __restrict__ scores,
    const void* __restrict__ gold_raw,
    const int* __restrict__ mask,
    const float* __restrict__ trans,
    float* __restrict__ out)
{
    const int bid = blockIdx.x;
    const int lane = threadIdx.x;
    const bool act = (lane < LN / 2);

    __shared__ float sh_w[2][LN];
    __shared__ int sh_k[2];

    int b;
    if (bid < BN * NC) {
        b = bid >> 4;
        const int c = bid & (NC - 1);
        const int j0 = act ? 2 * lane : 0;
        const int j1 = act ? 2 * lane + 1 : 0;

        // E columns for this lane's pair, packed over i-pairs; exp(-10000) == 0
        unsigned long long Ea[LN / 2], Eb[LN / 2];
#pragma unroll
        for (int q = 0; q < LN / 2; q++) {
            float lo = __expf(trans[(2 * q) * LN + j0]);
            float hi = __expf(trans[(2 * q + 1) * LN + j0]);
            PACK_F32X2_(Ea[q], lo, hi);
            lo = __expf(trans[(2 * q) * LN + j1]);
            hi = __expf(trans[(2 * q + 1) * LN + j1]);
            PACK_F32X2_(Eb[q], lo, hi);
        }

        float u0 = 1.0f, u1 = 1.0f;
        float log_in = 0.f;          // log(sum at start of the true chunk)

        if (c > 0) {
            // ---- warmup: WU steps ending at t = c*CL, from ones ----
            const float* scw = scores + ((size_t)b * TN + c * CL - WU) * LN + j0;
            const int*   mpw = mask + (size_t)b * TN + c * CL - WU;
            int Kw;
            chunk_scan<WU>(scw, mpw, Ea, Eb, u0, u1, act, lane, sh_w, sh_k, &Kw);

            if (act) {
                unsigned long long up;
                PACK_F32X2_(up, u0, u1);
                *(unsigned long long*)&sh_w[0][2 * lane] = up;
            }
            __syncwarp();
            log_in = logf(sumvec(sh_w[0]));   // warmup K cancels in the ratio
        }

        // ---- true chunk: CL steps ----
        const float* scp = scores + ((size_t)b * TN + c * CL) * LN + j0;
        const int*   mp  = mask + (size_t)b * TN + c * CL;
        int K;
        chunk_scan<CL>(scp, mp, Ea, Eb, u0, u1, act, lane, sh_w, sh_k, &K);

        if (act) {
            unsigned long long up;
            PACK_F32X2_(up, u0, u1);
            *(unsigned long long*)&sh_w[0][2 * lane] = up;
        }
        __syncwarp();
        const float sum = sumvec(sh_w[0]);

        if (lane == 0)
            g_S[b][c] = (float)K * 0.6931471805599453f + logf(sum) - log_in;

        if (c == NC - 1 && lane == (END_I >> 1))   // lane 23 owns column 47 = END
            g_tailEND[b] = logf(u1) - logf(sum);
    } else {
        // ---- tg gold-path energy (one warp per batch) ----
        b = bid - BN * NC;

        // gold declared int64; JAX (x64 off) materializes int32 — detect via ballot:
        // true int64 => every odd 32-bit word is 0 (labels < 48).
        const int* g32 = (const int*)gold_raw;
        const int ok = (g32[2 * lane + 1] == 0) && (g32[2 * (lane + 32) + 1] == 0);
        const int is64 = (__ballot_sync(0xffffffffu, ok) == 0xffffffffu);

        float sum = 0.f;
#pragma unroll
        for (int t = lane; t < TN; t += 32) {
            const long long li = (long long)b * TN + t;
            const int g = is64 ? g32[2 * li] : g32[li];   // little-endian low word
            const float v = scores[li * LN] + trans[g];   // crf[t+1,b,0,g]
            if (mask[li]) sum += v;
        }
        if (lane == 0) sum += trans[START_I];             // t=0 term: trans[0][START]

        sum = warp_sum(sum);
        if (lane == 0) g_tg[b] = sum;
    }

    // ---- per-batch arrival; last of NC+1 CTAs stitches ----
    __threadfence();
    unsigned r = 0;
    if (lane == 0) r = atomicAdd(&g_bd[b], 1u);
    r = __shfl_sync(0xffffffffu, r, 0);
    if (r == NC) {                        // 17th arrival
        __threadfence();
        float s = (lane < NC) ? g_S[b][lane] : 0.f;
        s = warp_sum(s);
        const float val = s + g_tailEND[b] - g_tg[b];
        if (lane == 0) {
            g_val[b] = val;
            g_bd[b] = 0u;                 // reset for next graph replay
        }
        __threadfence();
        unsigned r2 = 0;
        if (lane == 0) r2 = atomicAdd(&g_done, 1u);
        r2 = __shfl_sync(0xffffffffu, r2, 0);
        if (r2 == BN - 1) {               // last batch: deterministic final combine
            __threadfence();
            float v = g_val[lane] + g_val[lane + 32];
            v = warp_sum(v);
            if (lane == 0) {
                out[0] = v / (float)BN;
                g_done = 0u;              // reset for next graph replay
            }
        }
    }
}

extern "C" void kernel_launch(void* const* d_in, const int* in_sizes, int n_in,
                              void* d_out, int out_size)
{
    const float* scores = (const float*)d_in[0];
    const void*  gold   = (const void*)d_in[1];
    const int*   mask   = (const int*)d_in[2];
    const float* trans  = (const float*)d_in[3];
    float*       out    = (float*)d_out;

    crf_main_kernel<<<BN * NC + BN, 32>>>(scores, gold, mask, trans, out);
}